// round 12
// baseline (speedup 1.0000x reference)
#include <cuda_runtime.h>

#define DIM 16
#define TILE_ROWS 512
#define ROW_WORDS 20            /* 16 data floats + 4 pad -> 80B row stride */
#define TILE_WORDS (TILE_ROWS * ROW_WORDS)

// Folded weights: out = chem @ M^T + c, where M = Wo @ Wv, c = Wo @ bv + bo
__device__ __align__(16) float g_M[DIM * DIM];  // M[j][i], row-major
__device__ __align__(16) float g_c[DIM];

// ---------------------------------------------------------------------------
// Tiny prep kernel: fold the two 16x16 matmuls + biases into one matrix.
// ---------------------------------------------------------------------------
__global__ void prep_kernel(const float* __restrict__ in_w,   // [48,16]
                            const float* __restrict__ in_b,   // [48]
                            const float* __restrict__ out_w,  // [16,16]
                            const float* __restrict__ out_b)  // [16]
{
    const int t = threadIdx.x;           // 0..255
    const int j = t >> 4;
    const int i = t & 15;
    float s = 0.f;
#pragma unroll
    for (int k = 0; k < DIM; ++k)
        s += out_w[j * DIM + k] * in_w[(2 * DIM + k) * DIM + i];
    g_M[j * DIM + i] = s;
    if (i == 0) {
        float c = out_b[j];
#pragma unroll
        for (int k = 0; k < DIM; ++k)
            c += out_w[j * DIM + k] * in_b[2 * DIM + k];
        g_c[j] = c;
    }
}

// packed f32x2 FMA (Blackwell; only reachable via PTX)
__device__ __forceinline__ unsigned long long ffma2(unsigned long long a,
                                                    unsigned long long b,
                                                    unsigned long long c)
{
    unsigned long long d;
    asm("fma.rn.f32x2 %0, %1, %2, %3;" : "=l"(d) : "l"(a), "l"(b), "l"(c));
    return d;
}

// ---------------------------------------------------------------------------
// Two-phase tile kernel.
//  Phase 1: cp.async.cg stages a 512-row tile (32KB of data) into smem with
//           perfectly coalesced 512B-per-warp-instruction loads (128B/wf).
//           Rows are padded to 80B so the compute phase is bank-conflict-free.
//  Phase 2: 4 threads/row x 4 output cols/thread (weights in 64 regs),
//           inputs read from smem (broadcast within each 4-lane group, the
//           8 row addresses per warp hit 8 distinct bank groups).
// ---------------------------------------------------------------------------
__global__ void __launch_bounds__(256, 2)
matvec_kernel(const float* __restrict__ chem, float* __restrict__ out, int rows)
{
    __shared__ __align__(16) float tile[TILE_WORDS];

    const int tid = threadIdx.x;
    const size_t row_base = (size_t)blockIdx.x * TILE_ROWS;

    // ---- Phase 1: stage tile into smem via cp.async ----
    {
        const char* gbase =
            reinterpret_cast<const char*>(chem + row_base * DIM);
#pragma unroll
        for (int k = 0; k < 8; ++k) {
            const int c   = tid + k * 256;        // 16B chunk index, 0..2047
            const int r   = c >> 2;               // row within tile
            const int sub = c & 3;                // 16B chunk within row
            const unsigned smem_addr = (unsigned)
                __cvta_generic_to_shared(&tile[r * ROW_WORDS + sub * 4]);
            const char* gptr = gbase + (size_t)c * 16;
            asm volatile("cp.async.cg.shared.global [%0], [%1], 16;\n"
                         :: "r"(smem_addr), "l"(gptr));
        }
        asm volatile("cp.async.commit_group;\n");
    }

    // ---- Load weights while the tile is in flight ----
    const int e  = tid & 3;            // 4 threads per row
    const int jg = e * 4;              // first of this thread's 4 output cols
    unsigned long long w[4][8];
    float c4[4];
#pragma unroll
    for (int j = 0; j < 4; ++j) {
        const unsigned long long* wp =
            reinterpret_cast<const unsigned long long*>(&g_M[(jg + j) * DIM]);
#pragma unroll
        for (int i2 = 0; i2 < 8; ++i2) w[j][i2] = wp[i2];
        c4[j] = g_c[jg + j];
    }

    asm volatile("cp.async.wait_group 0;\n");
    __syncthreads();

    // ---- Phase 2: compute. 64 rows per pass, 8 passes cover 512 rows ----
    const int r0 = tid >> 2;           // this thread's row within the pass
#pragma unroll
    for (int p = 0; p < 8; ++p) {
        const int r = r0 + p * 64;
        const ulonglong2* sp =
            reinterpret_cast<const ulonglong2*>(&tile[r * ROW_WORDS]);
        ulonglong2 a0 = sp[0];
        ulonglong2 a1 = sp[1];
        ulonglong2 a2 = sp[2];
        ulonglong2 a3 = sp[3];
        const unsigned long long ap[8] = {a0.x, a0.y, a1.x, a1.y,
                                          a2.x, a2.y, a3.x, a3.y};

        float4 res;
        float* rp = reinterpret_cast<float*>(&res);
#pragma unroll
        for (int j = 0; j < 4; ++j) {
            unsigned long long acc =
                (unsigned long long)__float_as_uint(c4[j]);
#pragma unroll
            for (int i2 = 0; i2 < 8; ++i2)
                acc = ffma2(ap[i2], w[j][i2], acc);
            rp[j] = __uint_as_float((unsigned int)acc) +
                    __uint_as_float((unsigned int)(acc >> 32));
        }

        // warp store: lanes cover 8 consecutive rows x 64B = 512B contiguous
        reinterpret_cast<float4*>(out + (row_base + r) * DIM)[e] = res;
    }
}

extern "C" void kernel_launch(void* const* d_in, const int* in_sizes, int n_in,
                              void* d_out, int out_size)
{
    // inputs: 0=fp_16 (UNUSED), 1=chem_16, 2=in_proj_weight, 3=in_proj_bias,
    //         4=out_proj_weight, 5=out_proj_bias
    const float* chem  = (const float*)d_in[1];
    const float* in_w  = (const float*)d_in[2];
    const float* in_b  = (const float*)d_in[3];
    const float* out_w = (const float*)d_in[4];
    const float* out_b = (const float*)d_in[5];
    float* out = (float*)d_out;

    const int rows = in_sizes[1] / DIM;   // 2,097,152 (divisible by 512)

    prep_kernel<<<1, 256>>>(in_w, in_b, out_w, out_b);

    const int blocks = rows / TILE_ROWS;  // 4096 one-tile blocks
    matvec_kernel<<<blocks, 256>>>(chem, out, rows);
}

// round 13
// speedup vs baseline: 1.5053x; 1.5053x over previous
#include <cuda_runtime.h>

#define DIM 16
#define TILE_ROWS 512
#define ROW_WORDS 20            /* 16 data floats + 4 pad -> 80B row stride */
#define TILE_WORDS (TILE_ROWS * ROW_WORDS)

// Folded weights: out = chem @ M^T + c, where M = Wo @ Wv, c = Wo @ bv + bo
__device__ __align__(16) float g_M[DIM * DIM];  // M[j][i], row-major
__device__ __align__(16) float g_c[DIM];

// ---------------------------------------------------------------------------
// Tiny prep kernel: fold the two 16x16 matmuls + biases into one matrix.
// ---------------------------------------------------------------------------
__global__ void prep_kernel(const float* __restrict__ in_w,   // [48,16]
                            const float* __restrict__ in_b,   // [48]
                            const float* __restrict__ out_w,  // [16,16]
                            const float* __restrict__ out_b)  // [16]
{
    const int t = threadIdx.x;           // 0..255
    const int j = t >> 4;
    const int i = t & 15;
    float s = 0.f;
#pragma unroll
    for (int k = 0; k < DIM; ++k)
        s += out_w[j * DIM + k] * in_w[(2 * DIM + k) * DIM + i];
    g_M[j * DIM + i] = s;
    if (i == 0) {
        float c = out_b[j];
#pragma unroll
        for (int k = 0; k < DIM; ++k)
            c += out_w[j * DIM + k] * in_b[2 * DIM + k];
        g_c[j] = c;
    }
}

// packed f32x2 FMA (Blackwell; only reachable via PTX)
__device__ __forceinline__ unsigned long long ffma2(unsigned long long a,
                                                    unsigned long long b,
                                                    unsigned long long c)
{
    unsigned long long d;
    asm("fma.rn.f32x2 %0, %1, %2, %3;" : "=l"(d) : "l"(a), "l"(b), "l"(c));
    return d;
}

// ---------------------------------------------------------------------------
// Two-phase tile kernel.
//  Phase 1: cp.async.cg stages a 512-row tile (32KB of data) into smem with
//           perfectly coalesced 512B-per-warp-instruction loads (128B/wf).
//           Rows are padded to 80B so the compute phase is bank-conflict-free.
//  Phase 2: 4 threads/row x 4 output cols/thread (weights in 64 regs),
//           inputs read from smem (broadcast within each 4-lane group, the
//           8 row addresses per warp hit 8 distinct bank groups).
// ---------------------------------------------------------------------------
__global__ void __launch_bounds__(256, 2)
matvec_kernel(const float* __restrict__ chem, float* __restrict__ out, int rows)
{
    __shared__ __align__(16) float tile[TILE_WORDS];

    const int tid = threadIdx.x;
    const size_t row_base = (size_t)blockIdx.x * TILE_ROWS;

    // ---- Phase 1: stage tile into smem via cp.async ----
    {
        const char* gbase =
            reinterpret_cast<const char*>(chem + row_base * DIM);
#pragma unroll
        for (int k = 0; k < 8; ++k) {
            const int c   = tid + k * 256;        // 16B chunk index, 0..2047
            const int r   = c >> 2;               // row within tile
            const int sub = c & 3;                // 16B chunk within row
            const unsigned smem_addr = (unsigned)
                __cvta_generic_to_shared(&tile[r * ROW_WORDS + sub * 4]);
            const char* gptr = gbase + (size_t)c * 16;
            asm volatile("cp.async.cg.shared.global [%0], [%1], 16;\n"
                         :: "r"(smem_addr), "l"(gptr));
        }
        asm volatile("cp.async.commit_group;\n");
    }

    // ---- Load weights while the tile is in flight ----
    const int e  = tid & 3;            // 4 threads per row
    const int jg = e * 4;              // first of this thread's 4 output cols
    unsigned long long w[4][8];
    float c4[4];
#pragma unroll
    for (int j = 0; j < 4; ++j) {
        const unsigned long long* wp =
            reinterpret_cast<const unsigned long long*>(&g_M[(jg + j) * DIM]);
#pragma unroll
        for (int i2 = 0; i2 < 8; ++i2) w[j][i2] = wp[i2];
        c4[j] = g_c[jg + j];
    }

    asm volatile("cp.async.wait_group 0;\n");
    __syncthreads();

    // ---- Phase 2: compute. 64 rows per pass, 8 passes cover 512 rows ----
    const int r0 = tid >> 2;           // this thread's row within the pass
#pragma unroll
    for (int p = 0; p < 8; ++p) {
        const int r = r0 + p * 64;
        const ulonglong2* sp =
            reinterpret_cast<const ulonglong2*>(&tile[r * ROW_WORDS]);
        ulonglong2 a0 = sp[0];
        ulonglong2 a1 = sp[1];
        ulonglong2 a2 = sp[2];
        ulonglong2 a3 = sp[3];
        const unsigned long long ap[8] = {a0.x, a0.y, a1.x, a1.y,
                                          a2.x, a2.y, a3.x, a3.y};

        float4 res;
        float* rp = reinterpret_cast<float*>(&res);
#pragma unroll
        for (int j = 0; j < 4; ++j) {
            unsigned long long acc =
                (unsigned long long)__float_as_uint(c4[j]);
#pragma unroll
            for (int i2 = 0; i2 < 8; ++i2)
                acc = ffma2(ap[i2], w[j][i2], acc);
            rp[j] = __uint_as_float((unsigned int)acc) +
                    __uint_as_float((unsigned int)(acc >> 32));
        }

        // warp store: lanes cover 8 consecutive rows x 64B = 512B contiguous
        reinterpret_cast<float4*>(out + (row_base + r) * DIM)[e] = res;
    }
}

extern "C" void kernel_launch(void* const* d_in, const int* in_sizes, int n_in,
                              void* d_out, int out_size)
{
    // inputs: 0=fp_16 (UNUSED), 1=chem_16, 2=in_proj_weight, 3=in_proj_bias,
    //         4=out_proj_weight, 5=out_proj_bias
    const float* chem  = (const float*)d_in[1];
    const float* in_w  = (const float*)d_in[2];
    const float* in_b  = (const float*)d_in[3];
    const float* out_w = (const float*)d_in[4];
    const float* out_b = (const float*)d_in[5];
    float* out = (float*)d_out;

    const int rows = in_sizes[1] / DIM;   // 2,097,152 (divisible by 512)

    prep_kernel<<<1, 256>>>(in_w, in_b, out_w, out_b);

    const int blocks = rows / TILE_ROWS;  // 4096 one-tile blocks
    matvec_kernel<<<blocks, 256>>>(chem, out, rows);
}